// round 10
// baseline (speedup 1.0000x reference)
#include <cuda_runtime.h>
#include <cuda_fp16.h>
#include <cstdint>
#include <cstddef>

// ---------------------------------------------------------------------------
// QDense == one dense 4096x4096x4096 GEMM:
//     out[m,n] = sum_k x[m,k] * Weff[n,k] + bias_eff[n]
// Weff[co*1024+o][ci*1024+i] = S[co][ci] * W_{Q[co][ci]}[o][i]
//
// R9->R10: HMMA floor is rt~8/SMSP (~232us); we're at 55% of it with 1 CTA/SM.
//   Shrink CTA to 128x128 / 256 thr / 110.6KB smem -> 2 CTAs/SM so one CTA's
//   barrier/cp-wait bubbles are covered by the other CTA's MMA stream.
// ---------------------------------------------------------------------------

#define IN_F   4096
#define OUT_F  4096
#define BATCH  4096
#define QOUT   1024
#define W_ELEMS (1024 * 1024)

#define BM 128
#define BN 128
#define BK 64                         // k half-elements per stage (128 B rows)
#define STAGES 3
#define KTILES (IN_F / BK)            // 64
#define THREADS 256

#define ROWB 144                      // padded row stride in bytes (72 halves)
#define A_ST_BYTES (BM * ROWB)        // 18432
#define B_ST_BYTES (BN * ROWB)        // 18432
#define STAGE_BYTES (A_ST_BYTES + B_ST_BYTES)    // 36864
#define SMEM_TOTAL (STAGES * STAGE_BYTES)        // 110592  (2 CTAs/SM)

// Scratch: device globals (the only legal scratch)
__device__ __half g_xh[(size_t)BATCH * IN_F];    // fp16 x     (32 MB)
__device__ __half g_wh[(size_t)OUT_F * IN_F];    // fp16 Weff  (32 MB)
__device__ float  g_bias[OUT_F];

__constant__ int   c_q[4][4] = {{0,1,2,3},{1,0,3,2},{2,3,0,1},{3,2,1,0}};
__constant__ float c_s[4][4] = {{ 1.f,-1.f,-1.f,-1.f},
                                { 1.f, 1.f, 1.f,-1.f},
                                { 1.f,-1.f, 1.f, 1.f},
                                { 1.f, 1.f,-1.f, 1.f}};

// ------------------------------- helpers -----------------------------------

__device__ __forceinline__ uint32_t smem_u32(const void* p) {
    uint32_t a;
    asm("{ .reg .u64 t; cvta.to.shared.u64 t, %1; cvt.u32.u64 %0, t; }"
        : "=r"(a) : "l"(p));
    return a;
}

__device__ __forceinline__ void cp16(uint32_t dst, const void* src) {
    asm volatile("cp.async.cg.shared.global [%0], [%1], 16;" :: "r"(dst), "l"(src));
}

__device__ __forceinline__ void cp_commit() {
    asm volatile("cp.async.commit_group;" ::: "memory");
}

template <int N>
__device__ __forceinline__ void cp_wait() {
    asm volatile("cp.async.wait_group %0;" :: "n"(N) : "memory");
}

__device__ __forceinline__ void ldmx4(uint32_t* r, uint32_t addr) {
    asm volatile(
        "ldmatrix.sync.aligned.m8n8.x4.shared.b16 {%0,%1,%2,%3}, [%4];"
        : "=r"(r[0]), "=r"(r[1]), "=r"(r[2]), "=r"(r[3]) : "r"(addr));
}

__device__ __forceinline__ void mma_f16(float* d, const uint32_t* a,
                                        uint32_t b0, uint32_t b1) {
    asm volatile(
        "mma.sync.aligned.m16n8k16.row.col.f32.f16.f16.f32 "
        "{%0,%1,%2,%3}, {%4,%5,%6,%7}, {%8,%9}, {%0,%1,%2,%3};"
        : "+f"(d[0]), "+f"(d[1]), "+f"(d[2]), "+f"(d[3])
        : "r"(a[0]), "r"(a[1]), "r"(a[2]), "r"(a[3]), "r"(b0), "r"(b1));
}

// ------------------------------ prep kernels --------------------------------

__global__ void k_half_x(const float* __restrict__ x) {
    size_t i = (size_t)blockIdx.x * blockDim.x + threadIdx.x;   // float4 idx
    float4 v = ((const float4*)x)[i];
    __half2 h0 = make_half2(__float2half_rn(v.x), __float2half_rn(v.y));
    __half2 h1 = make_half2(__float2half_rn(v.z), __float2half_rn(v.w));
    ((__half2*)g_xh)[2 * i]     = h0;
    ((__half2*)g_xh)[2 * i + 1] = h1;
}

__global__ void k_weff(const float* __restrict__ W0, const float* __restrict__ W1,
                       const float* __restrict__ W2, const float* __restrict__ W3) {
    size_t id = (size_t)blockIdx.x * blockDim.x + threadIdx.x;  // float4 idx
    int n  = (int)(id >> 10);
    int k4 = (int)(id & 1023);
    int co = n >> 10, o = n & 1023;
    int ci = k4 >> 8;
    int i4 = k4 & 255;
    int q   = c_q[co][ci];
    float s = c_s[co][ci];
    const float* Wq = (q == 0) ? W0 : (q == 1) ? W1 : (q == 2) ? W2 : W3;
    float4 w = ((const float4*)Wq)[(size_t)o * 256 + i4];
    __half2 h0 = make_half2(__float2half_rn(s * w.x), __float2half_rn(s * w.y));
    __half2 h1 = make_half2(__float2half_rn(s * w.z), __float2half_rn(s * w.w));
    ((__half2*)g_wh)[2 * id]     = h0;
    ((__half2*)g_wh)[2 * id + 1] = h1;
}

__global__ void k_bias(const float* __restrict__ b0, const float* __restrict__ b1,
                       const float* __restrict__ b2, const float* __restrict__ b3) {
    int n = blockIdx.x * blockDim.x + threadIdx.x;
    if (n >= OUT_F) return;
    int co = n >> 10, o = n & 1023;
    const float* B[4] = {b0, b1, b2, b3};
    float acc = 0.f;
#pragma unroll
    for (int ci = 0; ci < 4; ci++) acc += c_s[co][ci] * B[c_q[co][ci]][o];
    g_bias[n] = acc;
}

// ------------------------------- GEMM kernel --------------------------------

__device__ __forceinline__ void load_stage(uint32_t sb, int slot, int kt,
                                           const __half* __restrict__ aG,
                                           const __half* __restrict__ bG,
                                           int tid) {
    const uint32_t st = sb + slot * STAGE_BYTES;
    const int koff = kt * BK;        // in half-elements
    // A: 128 rows x 8 chunks of 16B = 1024 chunks; 4 per thread
#pragma unroll
    for (int j = 0; j < 4; j++) {
        int c   = tid + j * THREADS;
        int row = c >> 3;
        int ko  = c & 7;
        cp16(st + row * ROWB + ko * 16,
             aG + (size_t)row * IN_F + koff + ko * 8);
    }
    // B: 128 rows x 8 chunks = 1024 chunks; 4 per thread
#pragma unroll
    for (int j = 0; j < 4; j++) {
        int c   = tid + j * THREADS;
        int row = c >> 3;
        int ko  = c & 7;
        cp16(st + A_ST_BYTES + row * ROWB + ko * 16,
             bG + (size_t)row * IN_F + koff + ko * 8);
    }
}

__global__ void __launch_bounds__(THREADS, 2) k_gemm(float* __restrict__ out) {
    extern __shared__ char smem[];
    const uint32_t sb = smem_u32(smem);
    const int tid = threadIdx.x;
    const int wid = tid >> 5;
    const int lid = tid & 31;
    const int m0 = blockIdx.y * BM;
    const int n0 = blockIdx.x * BN;

    const int wm = wid & 3;            // 4 m-warps (32 rows each)
    const int wn = wid >> 2;           // 2 n-warps (64 cols each)
    const int gid = lid >> 2;          // 0..7
    const int tig = lid & 3;           // 0..3

    const __half* aG = g_xh + (size_t)m0 * IN_F;
    const __half* bG = g_wh + (size_t)n0 * IN_F;

    // ldmatrix per-lane base addresses (stage 0)
    const uint32_t aL0 = sb
        + (uint32_t)(wm * 32 + (lid & 15)) * ROWB + (uint32_t)(lid >> 4) * 16;
    const uint32_t bL0 = sb + A_ST_BYTES
        + (uint32_t)(wn * 64 + ((lid >> 4) * 8) + (lid & 7)) * ROWB
        + (uint32_t)((lid >> 3) & 1) * 16;

    float acc[2][8][4];
#pragma unroll
    for (int mf = 0; mf < 2; mf++)
#pragma unroll
        for (int nf = 0; nf < 8; nf++)
#pragma unroll
            for (int r = 0; r < 4; r++) acc[mf][nf][r] = 0.f;

    // prologue: stages 0,1
    load_stage(sb, 0, 0, aG, bG, tid); cp_commit();
    load_stage(sb, 1, 1, aG, bG, tid); cp_commit();

    int slot = 0;
    for (int kt = 0; kt < KTILES; kt++) {
        cp_wait<1>();
        __syncthreads();   // data ready + slot-being-refilled drained

        if (kt + 2 < KTILES) {
            int ns = slot + 2; if (ns >= STAGES) ns -= STAGES;
            load_stage(sb, ns, kt + 2, aG, bG, tid);
        }
        cp_commit();

        const uint32_t aS = aL0 + slot * STAGE_BYTES;
        const uint32_t bS = bL0 + slot * STAGE_BYTES;

        // 4 x k16 chunks per stage; kk byte offset = kk*32 (16 halves)
#pragma unroll
        for (int kk = 0; kk < 4; kk++) {
            uint32_t a[2][4];
            ldmx4(a[0], aS + kk * 32);                 // rows wm*32..+15
            ldmx4(a[1], aS + 16 * ROWB + kk * 32);     // rows +16..+31
#pragma unroll
            for (int np = 0; np < 4; np++) {           // pairs of n-tiles
                uint32_t bq[4];
                ldmx4(bq, bS + np * (16 * ROWB) + kk * 32);
                mma_f16(acc[0][2 * np],     a[0], bq[0], bq[1]);
                mma_f16(acc[1][2 * np],     a[1], bq[0], bq[1]);
                mma_f16(acc[0][2 * np + 1], a[0], bq[2], bq[3]);
                mma_f16(acc[1][2 * np + 1], a[1], bq[2], bq[3]);
            }
        }

        slot++; if (slot >= STAGES) slot = 0;
    }

    // ---- epilogue: acc + bias -> out ----
    float2 bv[8];
#pragma unroll
    for (int nf = 0; nf < 8; nf++) {
        const float* bp = g_bias + n0 + wn * 64 + nf * 8 + tig * 2;
        bv[nf] = make_float2(bp[0], bp[1]);
    }
#pragma unroll
    for (int mf = 0; mf < 2; mf++) {
        int r0 = m0 + wm * 32 + mf * 16 + gid;
#pragma unroll
        for (int nf = 0; nf < 8; nf++) {
            int c = n0 + wn * 64 + nf * 8 + tig * 2;
            float2 v0 = make_float2(acc[mf][nf][0] + bv[nf].x,
                                    acc[mf][nf][1] + bv[nf].y);
            float2 v1 = make_float2(acc[mf][nf][2] + bv[nf].x,
                                    acc[mf][nf][3] + bv[nf].y);
            *(float2*)(out + (size_t)r0 * OUT_F + c)       = v0;
            *(float2*)(out + (size_t)(r0 + 8) * OUT_F + c) = v1;
        }
    }
}

// ------------------------------- launcher -----------------------------------

extern "C" void kernel_launch(void* const* d_in, const int* in_sizes, int n_in,
                              void* d_out, int out_size) {
    // Identify inputs by element count (robust to metadata ordering):
    //   x: 16777216;  W_*: 1048576 each;  b_*: 1024 each (OUT_Q)
    const float* x = nullptr;
    const float* W[4] = {nullptr, nullptr, nullptr, nullptr};
    const float* b[4] = {nullptr, nullptr, nullptr, nullptr};
    int wn = 0, bn = 0;
    for (int i = 0; i < n_in; i++) {
        if (in_sizes[i] == BATCH * IN_F)    x = (const float*)d_in[i];
        else if (in_sizes[i] == W_ELEMS)    { if (wn < 4) W[wn++] = (const float*)d_in[i]; }
        else if (in_sizes[i] == QOUT)       { if (bn < 4) b[bn++] = (const float*)d_in[i]; }
    }
    if (!x || wn != 4 || bn != 4) return;

    cudaFuncSetAttribute(k_gemm, cudaFuncAttributeMaxDynamicSharedMemorySize,
                         SMEM_TOTAL);

    k_half_x<<<(BATCH * IN_F / 4) / 256, 256>>>(x);
    k_weff<<<(int)(((size_t)OUT_F * IN_F / 4) / 256), 256>>>(W[0], W[1], W[2], W[3]);
    k_bias<<<OUT_F / 256, 256>>>(b[0], b[1], b[2], b[3]);

    dim3 grid(OUT_F / BN, BATCH / BM);
    k_gemm<<<grid, THREADS, SMEM_TOTAL>>>((float*)d_out);
}

// round 11
// speedup vs baseline: 1.2842x; 1.2842x over previous
#include <cuda_runtime.h>
#include <cuda_fp16.h>
#include <cstdint>
#include <cstddef>

// ---------------------------------------------------------------------------
// QDense == one dense 4096x4096x4096 GEMM:
//     out[m,n] = sum_k x[m,k] * Weff[n,k] + bias_eff[n]
// Weff[co*1024+o][ci*1024+i] = S[co][ci] * W_{Q[co][ci]}[o][i]
//
// R10 (2 CTAs/SM, BN=128) REGRESSED -> reverted to R9 config (BN=256/512thr).
// R11: break warp phase-locking. smem crossbar load (~1930cyc/kt) is ~95% of
//   tensor load (~2048cyc/kt) but they serialize because all 16 warps run the
//   identical unrolled kk sequence after each barrier. Skew kk order per warp
//   so ldmatrix bursts and HMMA bursts interleave across warps.
// ---------------------------------------------------------------------------

#define IN_F   4096
#define OUT_F  4096
#define BATCH  4096
#define QOUT   1024
#define W_ELEMS (1024 * 1024)

#define BM 128
#define BN 256
#define BK 64                         // k half-elements per stage (128 B rows)
#define STAGES 3
#define KTILES (IN_F / BK)            // 64
#define THREADS 512

#define ROWB 144                      // padded row stride in bytes (72 halves)
#define A_ST_BYTES (BM * ROWB)        // 18432
#define B_ST_BYTES (BN * ROWB)        // 36864
#define STAGE_BYTES (A_ST_BYTES + B_ST_BYTES)    // 55296
#define SMEM_TOTAL (STAGES * STAGE_BYTES)        // 165888

// Scratch: device globals (the only legal scratch)
__device__ __half g_xh[(size_t)BATCH * IN_F];    // fp16 x     (32 MB)
__device__ __half g_wh[(size_t)OUT_F * IN_F];    // fp16 Weff  (32 MB)
__device__ float  g_bias[OUT_F];

__constant__ int   c_q[4][4] = {{0,1,2,3},{1,0,3,2},{2,3,0,1},{3,2,1,0}};
__constant__ float c_s[4][4] = {{ 1.f,-1.f,-1.f,-1.f},
                                { 1.f, 1.f, 1.f,-1.f},
                                { 1.f,-1.f, 1.f, 1.f},
                                { 1.f, 1.f,-1.f, 1.f}};

// ------------------------------- helpers -----------------------------------

__device__ __forceinline__ uint32_t smem_u32(const void* p) {
    uint32_t a;
    asm("{ .reg .u64 t; cvta.to.shared.u64 t, %1; cvt.u32.u64 %0, t; }"
        : "=r"(a) : "l"(p));
    return a;
}

__device__ __forceinline__ void cp16(uint32_t dst, const void* src) {
    asm volatile("cp.async.cg.shared.global [%0], [%1], 16;" :: "r"(dst), "l"(src));
}

__device__ __forceinline__ void cp_commit() {
    asm volatile("cp.async.commit_group;" ::: "memory");
}

template <int N>
__device__ __forceinline__ void cp_wait() {
    asm volatile("cp.async.wait_group %0;" :: "n"(N) : "memory");
}

__device__ __forceinline__ void ldmx4(uint32_t* r, uint32_t addr) {
    asm volatile(
        "ldmatrix.sync.aligned.m8n8.x4.shared.b16 {%0,%1,%2,%3}, [%4];"
        : "=r"(r[0]), "=r"(r[1]), "=r"(r[2]), "=r"(r[3]) : "r"(addr));
}

__device__ __forceinline__ void mma_f16(float* d, const uint32_t* a,
                                        uint32_t b0, uint32_t b1) {
    asm volatile(
        "mma.sync.aligned.m16n8k16.row.col.f32.f16.f16.f32 "
        "{%0,%1,%2,%3}, {%4,%5,%6,%7}, {%8,%9}, {%0,%1,%2,%3};"
        : "+f"(d[0]), "+f"(d[1]), "+f"(d[2]), "+f"(d[3])
        : "r"(a[0]), "r"(a[1]), "r"(a[2]), "r"(a[3]), "r"(b0), "r"(b1));
}

// ------------------------------ prep kernels --------------------------------

__global__ void k_half_x(const float* __restrict__ x) {
    size_t i = (size_t)blockIdx.x * blockDim.x + threadIdx.x;   // float4 idx
    float4 v = ((const float4*)x)[i];
    __half2 h0 = make_half2(__float2half_rn(v.x), __float2half_rn(v.y));
    __half2 h1 = make_half2(__float2half_rn(v.z), __float2half_rn(v.w));
    ((__half2*)g_xh)[2 * i]     = h0;
    ((__half2*)g_xh)[2 * i + 1] = h1;
}

__global__ void k_weff(const float* __restrict__ W0, const float* __restrict__ W1,
                       const float* __restrict__ W2, const float* __restrict__ W3) {
    size_t id = (size_t)blockIdx.x * blockDim.x + threadIdx.x;  // float4 idx
    int n  = (int)(id >> 10);
    int k4 = (int)(id & 1023);
    int co = n >> 10, o = n & 1023;
    int ci = k4 >> 8;
    int i4 = k4 & 255;
    int q   = c_q[co][ci];
    float s = c_s[co][ci];
    const float* Wq = (q == 0) ? W0 : (q == 1) ? W1 : (q == 2) ? W2 : W3;
    float4 w = ((const float4*)Wq)[(size_t)o * 256 + i4];
    __half2 h0 = make_half2(__float2half_rn(s * w.x), __float2half_rn(s * w.y));
    __half2 h1 = make_half2(__float2half_rn(s * w.z), __float2half_rn(s * w.w));
    ((__half2*)g_wh)[2 * id]     = h0;
    ((__half2*)g_wh)[2 * id + 1] = h1;
}

__global__ void k_bias(const float* __restrict__ b0, const float* __restrict__ b1,
                       const float* __restrict__ b2, const float* __restrict__ b3) {
    int n = blockIdx.x * blockDim.x + threadIdx.x;
    if (n >= OUT_F) return;
    int co = n >> 10, o = n & 1023;
    const float* B[4] = {b0, b1, b2, b3};
    float acc = 0.f;
#pragma unroll
    for (int ci = 0; ci < 4; ci++) acc += c_s[co][ci] * B[c_q[co][ci]][o];
    g_bias[n] = acc;
}

// ------------------------------- GEMM kernel --------------------------------

__device__ __forceinline__ void load_stage(uint32_t sb, int slot, int kt,
                                           const __half* __restrict__ aG,
                                           const __half* __restrict__ bG,
                                           int tid) {
    const uint32_t st = sb + slot * STAGE_BYTES;
    const int koff = kt * BK;        // in half-elements
#pragma unroll
    for (int j = 0; j < 2; j++) {
        int c   = tid + j * THREADS;
        int row = c >> 3;
        int ko  = c & 7;
        cp16(st + row * ROWB + ko * 16,
             aG + (size_t)row * IN_F + koff + ko * 8);
    }
#pragma unroll
    for (int j = 0; j < 4; j++) {
        int c   = tid + j * THREADS;
        int row = c >> 3;
        int ko  = c & 7;
        cp16(st + A_ST_BYTES + row * ROWB + ko * 16,
             bG + (size_t)row * IN_F + koff + ko * 8);
    }
}

__global__ void __launch_bounds__(THREADS, 1) k_gemm(float* __restrict__ out) {
    extern __shared__ char smem[];
    const uint32_t sb = smem_u32(smem);
    const int tid = threadIdx.x;
    const int wid = tid >> 5;
    const int lid = tid & 31;
    const int m0 = blockIdx.y * BM;
    const int n0 = blockIdx.x * BN;

    const int wm = wid & 3;            // 4 m-warps (32 rows each)
    const int wn = wid >> 2;           // 4 n-warps (64 cols each)
    const int gid = lid >> 2;          // 0..7
    const int tig = lid & 3;           // 0..3
    const int kskew = wid & 3;         // per-warp kk rotation (phase de-lock)

    const __half* aG = g_xh + (size_t)m0 * IN_F;
    const __half* bG = g_wh + (size_t)n0 * IN_F;

    // ldmatrix per-lane base addresses (stage 0)
    const uint32_t aL0 = sb
        + (uint32_t)(wm * 32 + (lid & 15)) * ROWB + (uint32_t)(lid >> 4) * 16;
    const uint32_t bL0 = sb + A_ST_BYTES
        + (uint32_t)(wn * 64 + ((lid >> 4) * 8) + (lid & 7)) * ROWB
        + (uint32_t)((lid >> 3) & 1) * 16;

    float acc[2][8][4];
#pragma unroll
    for (int mf = 0; mf < 2; mf++)
#pragma unroll
        for (int nf = 0; nf < 8; nf++)
#pragma unroll
            for (int r = 0; r < 4; r++) acc[mf][nf][r] = 0.f;

    // prologue: stages 0,1
    load_stage(sb, 0, 0, aG, bG, tid); cp_commit();
    load_stage(sb, 1, 1, aG, bG, tid); cp_commit();

    int slot = 0;
    for (int kt = 0; kt < KTILES; kt++) {
        cp_wait<1>();
        __syncthreads();   // data ready + slot-being-refilled drained

        if (kt + 2 < KTILES) {
            int ns = slot + 2; if (ns >= STAGES) ns -= STAGES;
            load_stage(sb, ns, kt + 2, aG, bG, tid);
        }
        cp_commit();

        const uint32_t aS = aL0 + slot * STAGE_BYTES;
        const uint32_t bS = bL0 + slot * STAGE_BYTES;

        // 4 x k16 chunks; each warp walks them in a rotated order so the 16
        // warps' ldmatrix bursts and HMMA bursts interleave instead of
        // phase-locking on the smem port after each barrier.
#pragma unroll
        for (int kkr = 0; kkr < 4; kkr++) {
            const int kk = (kkr + kskew) & 3;
            uint32_t a[2][4];
            ldmx4(a[0], aS + kk * 32);                 // rows wm*32..+15
            ldmx4(a[1], aS + 16 * ROWB + kk * 32);     // rows +16..+31
#pragma unroll
            for (int np = 0; np < 4; np++) {           // pairs of n-tiles
                uint32_t bq[4];
                ldmx4(bq, bS + np * (16 * ROWB) + kk * 32);
                mma_f16(acc[0][2 * np],     a[0], bq[0], bq[1]);
                mma_f16(acc[1][2 * np],     a[1], bq[0], bq[1]);
                mma_f16(acc[0][2 * np + 1], a[0], bq[2], bq[3]);
                mma_f16(acc[1][2 * np + 1], a[1], bq[2], bq[3]);
            }
        }

        slot++; if (slot >= STAGES) slot = 0;
    }

    // ---- epilogue: acc + bias -> out ----
    float2 bv[8];
#pragma unroll
    for (int nf = 0; nf < 8; nf++) {
        const float* bp = g_bias + n0 + wn * 64 + nf * 8 + tig * 2;
        bv[nf] = make_float2(bp[0], bp[1]);
    }
#pragma unroll
    for (int mf = 0; mf < 2; mf++) {
        int r0 = m0 + wm * 32 + mf * 16 + gid;
#pragma unroll
        for (int nf = 0; nf < 8; nf++) {
            int c = n0 + wn * 64 + nf * 8 + tig * 2;
            float2 v0 = make_float2(acc[mf][nf][0] + bv[nf].x,
                                    acc[mf][nf][1] + bv[nf].y);
            float2 v1 = make_float2(acc[mf][nf][2] + bv[nf].x,
                                    acc[mf][nf][3] + bv[nf].y);
            *(float2*)(out + (size_t)r0 * OUT_F + c)       = v0;
            *(float2*)(out + (size_t)(r0 + 8) * OUT_F + c) = v1;
        }
    }
}

// ------------------------------- launcher -----------------------------------

extern "C" void kernel_launch(void* const* d_in, const int* in_sizes, int n_in,
                              void* d_out, int out_size) {
    // Identify inputs by element count (robust to metadata ordering):
    //   x: 16777216;  W_*: 1048576 each;  b_*: 1024 each (OUT_Q)
    const float* x = nullptr;
    const float* W[4] = {nullptr, nullptr, nullptr, nullptr};
    const float* b[4] = {nullptr, nullptr, nullptr, nullptr};
    int wn = 0, bn = 0;
    for (int i = 0; i < n_in; i++) {
        if (in_sizes[i] == BATCH * IN_F)    x = (const float*)d_in[i];
        else if (in_sizes[i] == W_ELEMS)    { if (wn < 4) W[wn++] = (const float*)d_in[i]; }
        else if (in_sizes[i] == QOUT)       { if (bn < 4) b[bn++] = (const float*)d_in[i]; }
    }
    if (!x || wn != 4 || bn != 4) return;

    cudaFuncSetAttribute(k_gemm, cudaFuncAttributeMaxDynamicSharedMemorySize,
                         SMEM_TOTAL);

    k_half_x<<<(BATCH * IN_F / 4) / 256, 256>>>(x);
    k_weff<<<(int)(((size_t)OUT_F * IN_F / 4) / 256), 256>>>(W[0], W[1], W[2], W[3]);
    k_bias<<<OUT_F / 256, 256>>>(b[0], b[1], b[2], b[3]);

    dim3 grid(OUT_F / BN, BATCH / BM);
    k_gemm<<<grid, THREADS, SMEM_TOTAL>>>((float*)d_out);
}

// round 12
// speedup vs baseline: 1.3654x; 1.0632x over previous
#include <cuda_runtime.h>
#include <cuda_fp16.h>
#include <cstdint>
#include <cstddef>

// ---------------------------------------------------------------------------
// QDense == one dense 4096x4096x4096 GEMM:
//     out[m,n] = sum_k x[m,k] * Weff[n,k] + bias_eff[n]
// Weff[co*1024+o][ci*1024+i] = S[co][ci] * W_{Q[co][ci]}[o][i]
//
// R11->R12: kskew reverted (regressed). New lever: intra-warp software
//   pipelining of ldmatrix fragments (double-buffered A tiles and B quads) so
//   every ldmatrix has >=4 independent HMMAs between issue and use, hiding the
//   ~30cyc LDS latency that shows up as low issue% with tensor stuck ~54%.
// ---------------------------------------------------------------------------

#define IN_F   4096
#define OUT_F  4096
#define BATCH  4096
#define QOUT   1024
#define W_ELEMS (1024 * 1024)

#define BM 128
#define BN 256
#define BK 64                         // k half-elements per stage (128 B rows)
#define STAGES 3
#define KTILES (IN_F / BK)            // 64
#define THREADS 512

#define ROWB 144                      // padded row stride in bytes (72 halves)
#define A_ST_BYTES (BM * ROWB)        // 18432
#define B_ST_BYTES (BN * ROWB)        // 36864
#define STAGE_BYTES (A_ST_BYTES + B_ST_BYTES)    // 55296
#define SMEM_TOTAL (STAGES * STAGE_BYTES)        // 165888

// Scratch: device globals (the only legal scratch)
__device__ __half g_xh[(size_t)BATCH * IN_F];    // fp16 x     (32 MB)
__device__ __half g_wh[(size_t)OUT_F * IN_F];    // fp16 Weff  (32 MB)
__device__ float  g_bias[OUT_F];

__constant__ int   c_q[4][4] = {{0,1,2,3},{1,0,3,2},{2,3,0,1},{3,2,1,0}};
__constant__ float c_s[4][4] = {{ 1.f,-1.f,-1.f,-1.f},
                                { 1.f, 1.f, 1.f,-1.f},
                                { 1.f,-1.f, 1.f, 1.f},
                                { 1.f, 1.f,-1.f, 1.f}};

// ------------------------------- helpers -----------------------------------

__device__ __forceinline__ uint32_t smem_u32(const void* p) {
    uint32_t a;
    asm("{ .reg .u64 t; cvta.to.shared.u64 t, %1; cvt.u32.u64 %0, t; }"
        : "=r"(a) : "l"(p));
    return a;
}

__device__ __forceinline__ void cp16(uint32_t dst, const void* src) {
    asm volatile("cp.async.cg.shared.global [%0], [%1], 16;" :: "r"(dst), "l"(src));
}

__device__ __forceinline__ void cp_commit() {
    asm volatile("cp.async.commit_group;" ::: "memory");
}

template <int N>
__device__ __forceinline__ void cp_wait() {
    asm volatile("cp.async.wait_group %0;" :: "n"(N) : "memory");
}

__device__ __forceinline__ void ldmx4(uint32_t* r, uint32_t addr) {
    asm volatile(
        "ldmatrix.sync.aligned.m8n8.x4.shared.b16 {%0,%1,%2,%3}, [%4];"
        : "=r"(r[0]), "=r"(r[1]), "=r"(r[2]), "=r"(r[3]) : "r"(addr));
}

__device__ __forceinline__ void mma_f16(float* d, const uint32_t* a,
                                        uint32_t b0, uint32_t b1) {
    asm volatile(
        "mma.sync.aligned.m16n8k16.row.col.f32.f16.f16.f32 "
        "{%0,%1,%2,%3}, {%4,%5,%6,%7}, {%8,%9}, {%0,%1,%2,%3};"
        : "+f"(d[0]), "+f"(d[1]), "+f"(d[2]), "+f"(d[3])
        : "r"(a[0]), "r"(a[1]), "r"(a[2]), "r"(a[3]), "r"(b0), "r"(b1));
}

// ------------------------------ prep kernels --------------------------------

__global__ void k_half_x(const float* __restrict__ x) {
    size_t i = (size_t)blockIdx.x * blockDim.x + threadIdx.x;   // float4 idx
    float4 v = ((const float4*)x)[i];
    __half2 h0 = make_half2(__float2half_rn(v.x), __float2half_rn(v.y));
    __half2 h1 = make_half2(__float2half_rn(v.z), __float2half_rn(v.w));
    ((__half2*)g_xh)[2 * i]     = h0;
    ((__half2*)g_xh)[2 * i + 1] = h1;
}

__global__ void k_weff(const float* __restrict__ W0, const float* __restrict__ W1,
                       const float* __restrict__ W2, const float* __restrict__ W3) {
    size_t id = (size_t)blockIdx.x * blockDim.x + threadIdx.x;  // float4 idx
    int n  = (int)(id >> 10);
    int k4 = (int)(id & 1023);
    int co = n >> 10, o = n & 1023;
    int ci = k4 >> 8;
    int i4 = k4 & 255;
    int q   = c_q[co][ci];
    float s = c_s[co][ci];
    const float* Wq = (q == 0) ? W0 : (q == 1) ? W1 : (q == 2) ? W2 : W3;
    float4 w = ((const float4*)Wq)[(size_t)o * 256 + i4];
    __half2 h0 = make_half2(__float2half_rn(s * w.x), __float2half_rn(s * w.y));
    __half2 h1 = make_half2(__float2half_rn(s * w.z), __float2half_rn(s * w.w));
    ((__half2*)g_wh)[2 * id]     = h0;
    ((__half2*)g_wh)[2 * id + 1] = h1;
}

__global__ void k_bias(const float* __restrict__ b0, const float* __restrict__ b1,
                       const float* __restrict__ b2, const float* __restrict__ b3) {
    int n = blockIdx.x * blockDim.x + threadIdx.x;
    if (n >= OUT_F) return;
    int co = n >> 10, o = n & 1023;
    const float* B[4] = {b0, b1, b2, b3};
    float acc = 0.f;
#pragma unroll
    for (int ci = 0; ci < 4; ci++) acc += c_s[co][ci] * B[c_q[co][ci]][o];
    g_bias[n] = acc;
}

// ------------------------------- GEMM kernel --------------------------------

__device__ __forceinline__ void load_stage(uint32_t sb, int slot, int kt,
                                           const __half* __restrict__ aG,
                                           const __half* __restrict__ bG,
                                           int tid) {
    const uint32_t st = sb + slot * STAGE_BYTES;
    const int koff = kt * BK;        // in half-elements
#pragma unroll
    for (int j = 0; j < 2; j++) {
        int c   = tid + j * THREADS;
        int row = c >> 3;
        int ko  = c & 7;
        cp16(st + row * ROWB + ko * 16,
             aG + (size_t)row * IN_F + koff + ko * 8);
    }
#pragma unroll
    for (int j = 0; j < 4; j++) {
        int c   = tid + j * THREADS;
        int row = c >> 3;
        int ko  = c & 7;
        cp16(st + A_ST_BYTES + row * ROWB + ko * 16,
             bG + (size_t)row * IN_F + koff + ko * 8);
    }
}

__global__ void __launch_bounds__(THREADS, 1) k_gemm(float* __restrict__ out) {
    extern __shared__ char smem[];
    const uint32_t sb = smem_u32(smem);
    const int tid = threadIdx.x;
    const int wid = tid >> 5;
    const int lid = tid & 31;
    const int m0 = blockIdx.y * BM;
    const int n0 = blockIdx.x * BN;

    const int wm = wid & 3;            // 4 m-warps (32 rows each)
    const int wn = wid >> 2;           // 4 n-warps (64 cols each)
    const int gid = lid >> 2;          // 0..7
    const int tig = lid & 3;           // 0..3

    const __half* aG = g_xh + (size_t)m0 * IN_F;
    const __half* bG = g_wh + (size_t)n0 * IN_F;

    // ldmatrix per-lane base addresses (stage 0)
    const uint32_t aL0 = sb
        + (uint32_t)(wm * 32 + (lid & 15)) * ROWB + (uint32_t)(lid >> 4) * 16;
    const uint32_t bL0 = sb + A_ST_BYTES
        + (uint32_t)(wn * 64 + ((lid >> 4) * 8) + (lid & 7)) * ROWB
        + (uint32_t)((lid >> 3) & 1) * 16;

    float acc[2][8][4];
#pragma unroll
    for (int mf = 0; mf < 2; mf++)
#pragma unroll
        for (int nf = 0; nf < 8; nf++)
#pragma unroll
            for (int r = 0; r < 4; r++) acc[mf][nf][r] = 0.f;

    // prologue: stages 0,1
    load_stage(sb, 0, 0, aG, bG, tid); cp_commit();
    load_stage(sb, 1, 1, aG, bG, tid); cp_commit();

    int slot = 0;
    for (int kt = 0; kt < KTILES; kt++) {
        cp_wait<1>();
        __syncthreads();   // data ready + slot-being-refilled drained

        if (kt + 2 < KTILES) {
            int ns = slot + 2; if (ns >= STAGES) ns -= STAGES;
            load_stage(sb, ns, kt + 2, aG, bG, tid);
        }
        cp_commit();

        const uint32_t aS = aL0 + slot * STAGE_BYTES;
        const uint32_t bS = bL0 + slot * STAGE_BYTES;

        // ---- software-pipelined fragment loop ----
        // Double-buffer A tiles (per kk) and B quads (per np): every ldmatrix
        // has the 4 MMAs of the previous np in flight to hide LDS latency.
        uint32_t a_cur[2][4], a_nxt[2][4], bq_cur[4], bq_nxt[4];
        ldmx4(a_cur[0], aS);
        ldmx4(a_cur[1], aS + 16 * ROWB);
        ldmx4(bq_cur, bS);

#pragma unroll
        for (int kk = 0; kk < 4; kk++) {
#pragma unroll
            for (int np = 0; np < 4; np++) {
                // prefetch next B quad (or next kk's A tiles + first B quad)
                if (np < 3) {
                    ldmx4(bq_nxt, bS + kk * 32 + (np + 1) * (16 * ROWB));
                } else if (kk < 3) {
                    ldmx4(a_nxt[0], aS + (kk + 1) * 32);
                    ldmx4(a_nxt[1], aS + 16 * ROWB + (kk + 1) * 32);
                    ldmx4(bq_nxt, bS + (kk + 1) * 32);
                }
                mma_f16(acc[0][2 * np],     a_cur[0], bq_cur[0], bq_cur[1]);
                mma_f16(acc[1][2 * np],     a_cur[1], bq_cur[0], bq_cur[1]);
                mma_f16(acc[0][2 * np + 1], a_cur[0], bq_cur[2], bq_cur[3]);
                mma_f16(acc[1][2 * np + 1], a_cur[1], bq_cur[2], bq_cur[3]);
#pragma unroll
                for (int r = 0; r < 4; r++) bq_cur[r] = bq_nxt[r];
            }
#pragma unroll
            for (int r = 0; r < 4; r++) {
                a_cur[0][r] = a_nxt[0][r];
                a_cur[1][r] = a_nxt[1][r];
            }
        }

        slot++; if (slot >= STAGES) slot = 0;
    }

    // ---- epilogue: acc + bias -> out ----
    float2 bv[8];
#pragma unroll
    for (int nf = 0; nf < 8; nf++) {
        const float* bp = g_bias + n0 + wn * 64 + nf * 8 + tig * 2;
        bv[nf] = make_float2(bp[0], bp[1]);
    }
#pragma unroll
    for (int mf = 0; mf < 2; mf++) {
        int r0 = m0 + wm * 32 + mf * 16 + gid;
#pragma unroll
        for (int nf = 0; nf < 8; nf++) {
            int c = n0 + wn * 64 + nf * 8 + tig * 2;
            float2 v0 = make_float2(acc[mf][nf][0] + bv[nf].x,
                                    acc[mf][nf][1] + bv[nf].y);
            float2 v1 = make_float2(acc[mf][nf][2] + bv[nf].x,
                                    acc[mf][nf][3] + bv[nf].y);
            *(float2*)(out + (size_t)r0 * OUT_F + c)       = v0;
            *(float2*)(out + (size_t)(r0 + 8) * OUT_F + c) = v1;
        }
    }
}

// ------------------------------- launcher -----------------------------------

extern "C" void kernel_launch(void* const* d_in, const int* in_sizes, int n_in,
                              void* d_out, int out_size) {
    // Identify inputs by element count (robust to metadata ordering):
    //   x: 16777216;  W_*: 1048576 each;  b_*: 1024 each (OUT_Q)
    const float* x = nullptr;
    const float* W[4] = {nullptr, nullptr, nullptr, nullptr};
    const float* b[4] = {nullptr, nullptr, nullptr, nullptr};
    int wn = 0, bn = 0;
    for (int i = 0; i < n_in; i++) {
        if (in_sizes[i] == BATCH * IN_F)    x = (const float*)d_in[i];
        else if (in_sizes[i] == W_ELEMS)    { if (wn < 4) W[wn++] = (const float*)d_in[i]; }
        else if (in_sizes[i] == QOUT)       { if (bn < 4) b[bn++] = (const float*)d_in[i]; }
    }
    if (!x || wn != 4 || bn != 4) return;

    cudaFuncSetAttribute(k_gemm, cudaFuncAttributeMaxDynamicSharedMemorySize,
                         SMEM_TOTAL);

    k_half_x<<<(BATCH * IN_F / 4) / 256, 256>>>(x);
    k_weff<<<(int)(((size_t)OUT_F * IN_F / 4) / 256), 256>>>(W[0], W[1], W[2], W[3]);
    k_bias<<<OUT_F / 256, 256>>>(b[0], b[1], b[2], b[3]);

    dim3 grid(OUT_F / BN, BATCH / BM);
    k_gemm<<<grid, THREADS, SMEM_TOTAL>>>((float*)d_out);
}